// round 4
// baseline (speedup 1.0000x reference)
#include <cuda_runtime.h>

// ---------------- grid geometry (single fused kernel) ----------------
// Level 0: S=80, HW4=1600, C=128 -> 16 img x 7 pix-chunks x 4 csplits = 448 blocks, 32 ch each
// Level 1: S=40, HW4=400,  C=256 -> 16 img x 2 pix-chunks x 8 csplits = 256 blocks, 32 ch each
// Level 2: S=20, HW4=100,  C=512 -> 16 img x 1 pix-chunk x 16 csplits = 256 blocks, 32 ch each
#define NB0 448
#define NB1 256
#define NB2 256
#define NB_TOT (NB0 + NB1 + NB2)   // 960

// ---------------- scratch ----------------
__device__ double g_part_sq[NB_TOT];   // per-block sum( m^2 * sum_c d^2 )
__device__ double g_part_m[NB_TOT];    // per-block sum( m )   (csplit==0 only, else 0)

// ---------------- block reduce (float -> thread 0 of warp 0) ----------------
__device__ __forceinline__ float block_reduce(float v) {
    #pragma unroll
    for (int o = 16; o > 0; o >>= 1) v += __shfl_down_sync(0xffffffffu, v, o);
    __shared__ float ws[8];
    const int lane = threadIdx.x & 31, wid = threadIdx.x >> 5;
    if (lane == 0) ws[wid] = v;
    __syncthreads();
    if (wid == 0) {
        v = (lane < 8) ? ws[lane] : 0.0f;
        #pragma unroll
        for (int o = 4; o > 0; o >>= 1) v += __shfl_down_sync(0xffffffffu, v, o);
    }
    return v;
}

// ---------------- per-level worker ----------------
// Thread owns one float4 of pixels; loops 32 channels; mask computed inline at end.
template <int S, int C, int CSPL>
__device__ __forceinline__ void level_work(
    const float* __restrict__ p, const float* __restrict__ t,
    const float* __restrict__ bboxes, const int* __restrict__ bidx, int nbox,
    int b, int chunk, int csplit)
{
    constexpr int HW  = S * S;
    constexpr int HW4 = HW / 4;
    constexpr int CPB = C / CSPL;      // 32 channels per block

    // ---- cache this image's boxes in shared ----
    __shared__ int   cnt;
    __shared__ float s_xc[64], s_yc[64], s_iw[64], s_ih[64];
    __shared__ int   s_xl[64], s_xr[64], s_yt[64], s_yd[64];
    if (threadIdx.x == 0) cnt = 0;
    __syncthreads();
    for (int i = threadIdx.x; i < nbox; i += blockDim.x) {
        if (bidx[i] == b) {
            int xc = (int)floorf(bboxes[4 * i + 0] * (float)S);
            int yc = (int)floorf(bboxes[4 * i + 1] * (float)S);
            int w  = (int)floorf(bboxes[4 * i + 2] * (float)S);
            int h  = (int)floorf(bboxes[4 * i + 3] * (float)S);
            int xl = max(xc - w / 2, 0), xr = min(xc + w / 2, S - 1);
            int yt = max(yc - h / 2, 0), yd = min(yc + h / 2, S - 1);
            float wd = (float)(xr - xl + 1), ht = (float)(yd - yt + 1);
            int q = atomicAdd(&cnt, 1);
            s_xc[q] = (float)xc; s_yc[q] = (float)yc;
            // STD^2*(w/2)^2 == w^2 for STD=2
            s_iw[q] = 1.0f / (wd * wd); s_ih[q] = 1.0f / (ht * ht);
            s_xl[q] = xl; s_xr[q] = xr; s_yt[q] = yt; s_yd[q] = yd;
        }
    }
    __syncthreads();
    const int n = cnt;

    const int pix4 = chunk * 256 + threadIdx.x;        // float4 index within image plane
    const bool valid = (pix4 < HW4);

    // ---- stream channels: acc_j = sum_c (p-t)^2 per component ----
    float4 acc0 = make_float4(0.f, 0.f, 0.f, 0.f);
    float4 acc1 = make_float4(0.f, 0.f, 0.f, 0.f);
    if (valid) {
        const float4* pp = (const float4*)p + (size_t)b * C * HW4 + (size_t)csplit * CPB * HW4 + pix4;
        const float4* tt = (const float4*)t + (size_t)b * C * HW4 + (size_t)csplit * CPB * HW4 + pix4;
        #pragma unroll 4
        for (int c = 0; c < CPB; c += 2) {
            float4 pv0 = pp[(size_t)c * HW4];
            float4 tv0 = tt[(size_t)c * HW4];
            float4 pv1 = pp[(size_t)(c + 1) * HW4];
            float4 tv1 = tt[(size_t)(c + 1) * HW4];
            float d;
            d = pv0.x - tv0.x; acc0.x += d * d;
            d = pv0.y - tv0.y; acc0.y += d * d;
            d = pv0.z - tv0.z; acc0.z += d * d;
            d = pv0.w - tv0.w; acc0.w += d * d;
            d = pv1.x - tv1.x; acc1.x += d * d;
            d = pv1.y - tv1.y; acc1.y += d * d;
            d = pv1.z - tv1.z; acc1.z += d * d;
            d = pv1.w - tv1.w; acc1.w += d * d;
        }
    }

    // ---- inline mask for the 4 pixels ----
    float msum = 0.0f;   // sum of m over owned pixels (for n_pos)
    float qsum = 0.0f;   // m^2 * sum_c d^2
    if (valid) {
        const int base = pix4 * 4;
        #pragma unroll
        for (int j = 0; j < 4; j++) {
            const int pixel = base + j;
            const int y = pixel / S, x = pixel % S;
            const float fx = (float)x, fy = (float)y;
            float m = 0.0f;
            for (int i = 0; i < n; i++) {
                if (x >= s_xl[i] && x <= s_xr[i] && y >= s_yt[i] && y <= s_yd[i]) {
                    float dx = fx - s_xc[i], dy = fy - s_yc[i];
                    float v = expf(-(dx * dx * s_iw[i] + dy * dy * s_ih[i]));
                    m = fmaxf(m, v);
                }
            }
            float a = (j == 0) ? acc0.x + acc1.x :
                      (j == 1) ? acc0.y + acc1.y :
                      (j == 2) ? acc0.z + acc1.z : acc0.w + acc1.w;
            qsum += m * m * a;
            msum += m;
        }
    }

    float qb = block_reduce(qsum);
    __syncthreads();
    float mb = block_reduce(csplit == 0 ? msum : 0.0f);
    if (threadIdx.x == 0) {
        g_part_sq[blockIdx.x] = (double)qb;
        g_part_m[blockIdx.x]  = (double)mb;
    }
}

// ---------------- fused kernel ----------------
__global__ void __launch_bounds__(256) fused_kernel(
    const float* __restrict__ p0, const float* __restrict__ t0,
    const float* __restrict__ p1, const float* __restrict__ t1,
    const float* __restrict__ p2, const float* __restrict__ t2,
    const float* __restrict__ bboxes, const int* __restrict__ bidx, int nbox)
{
    const int blk = blockIdx.x;
    if (blk < NB0) {
        // b = blk/28, rem = blk%28, chunk = rem/4, csplit = rem%4
        const int b = blk / 28, rem = blk % 28;
        level_work<80, 128, 4>(p0, t0, bboxes, bidx, nbox, b, rem / 4, rem % 4);
    } else if (blk < NB0 + NB1) {
        const int l = blk - NB0;
        const int b = l / 16, rem = l % 16;
        level_work<40, 256, 8>(p1, t1, bboxes, bidx, nbox, b, rem / 8, rem % 8);
    } else {
        const int l = blk - (NB0 + NB1);
        const int b = l / 16, csplit = l % 16;
        level_work<20, 512, 16>(p2, t2, bboxes, bidx, nbox, b, 0, csplit);
    }
}

// ---------------- finalize ----------------
__device__ __forceinline__ double sum_range(const double* a, int lo, int hi) {
    double s = 0.0;
    for (int i = lo + threadIdx.x; i < hi; i += blockDim.x) s += a[i];
    __shared__ double sd[256];
    sd[threadIdx.x] = s;
    __syncthreads();
    for (int o = 128; o > 0; o >>= 1) {
        if (threadIdx.x < o) sd[threadIdx.x] += sd[threadIdx.x + o];
        __syncthreads();
    }
    double r = sd[0];
    __syncthreads();
    return r;
}

__global__ void __launch_bounds__(256) finalize_kernel(float* __restrict__ out) {
    double q0 = sum_range(g_part_sq, 0, NB0);
    double q1 = sum_range(g_part_sq, NB0, NB0 + NB1);
    double q2 = sum_range(g_part_sq, NB0 + NB1, NB_TOT);
    double m0 = sum_range(g_part_m, 0, NB0);
    double m1 = sum_range(g_part_m, NB0, NB0 + NB1);
    double m2 = sum_range(g_part_m, NB0 + NB1, NB_TOT);
    if (threadIdx.x == 0) {
        double total = q0 / (128.0 * m0) + q1 / (256.0 * m1) + q2 / (512.0 * m2);
        out[0] = (float)(total / 3.0);
    }
}

extern "C" void kernel_launch(void* const* d_in, const int* in_sizes, int n_in,
                              void* d_out, int out_size)
{
    // metadata order is INTERLEAVED: pred0, true0, pred1, true1, pred2, true2
    const float* p0 = (const float*)d_in[0];
    const float* t0 = (const float*)d_in[1];
    const float* p1 = (const float*)d_in[2];
    const float* t1 = (const float*)d_in[3];
    const float* p2 = (const float*)d_in[4];
    const float* t2 = (const float*)d_in[5];
    const float* bboxes = (const float*)d_in[6];
    const int* bidx = (const int*)d_in[8];
    const int nbox = in_sizes[8];
    float* out = (float*)d_out;

    fused_kernel<<<NB_TOT, 256>>>(p0, t0, p1, t1, p2, t2, bboxes, bidx, nbox);
    finalize_kernel<<<1, 256>>>(out);
}